// round 1
// baseline (speedup 1.0000x reference)
#include <cuda_runtime.h>
#include <cuda_bf16.h>
#include <math.h>

#define BB 2
#define NQ 2048
#define NK 2048
#define DD 1024
#define HH 16
#define HDIM 64

// Scratch (allocation-free: __device__ globals)
__device__ float g_Q[(size_t)BB * NQ * DD];
__device__ float g_K[(size_t)BB * NK * DD];
__device__ float g_V[(size_t)BB * NK * DD];
__device__ float g_O[(size_t)BB * NQ * DD];

// ---------------------------------------------------------------------------
// Generic tiled GEMM: Y[m][n] = sum_k X[m][k] * W[n][k] + b[n]
// X: (M,K) row-major, W: (N,K) row-major. 64x64 block tile, 16 k-tile,
// 256 threads, 4x4 per-thread micro-tile.
// ---------------------------------------------------------------------------
__global__ void gemm_bias(const float* __restrict__ X, const float* __restrict__ W,
                          const float* __restrict__ b, float* __restrict__ Y,
                          int M, int N, int K) {
    __shared__ float Xs[64][17];
    __shared__ float Ws[64][17];
    int tid = threadIdx.x;
    int tx = tid % 16, ty = tid / 16;
    int row0 = blockIdx.y * 64, col0 = blockIdx.x * 64;

    float acc[4][4] = {};
    for (int kt = 0; kt < K; kt += 16) {
#pragma unroll
        for (int i = 0; i < 4; i++) {
            int idx = tid + i * 256;
            int r = idx >> 4, c = idx & 15;
            Xs[r][c] = X[(size_t)(row0 + r) * K + kt + c];
            Ws[r][c] = W[(size_t)(col0 + r) * K + kt + c];
        }
        __syncthreads();
#pragma unroll
        for (int kk = 0; kk < 16; kk++) {
            float xr[4], wr[4];
#pragma unroll
            for (int i = 0; i < 4; i++) xr[i] = Xs[ty * 4 + i][kk];
#pragma unroll
            for (int j = 0; j < 4; j++) wr[j] = Ws[tx * 4 + j][kk];
#pragma unroll
            for (int i = 0; i < 4; i++)
#pragma unroll
                for (int j = 0; j < 4; j++) acc[i][j] += xr[i] * wr[j];
        }
        __syncthreads();
    }
#pragma unroll
    for (int i = 0; i < 4; i++)
#pragma unroll
        for (int j = 0; j < 4; j++) {
            int r = row0 + ty * 4 + i, c = col0 + tx * 4 + j;
            Y[(size_t)r * N + c] = acc[i][j] + b[c];
        }
}

// ---------------------------------------------------------------------------
// xpos RoPE, in place on (B, N, H*HD). One thread per (row, head, pair).
// ---------------------------------------------------------------------------
__global__ void rope_kernel(float* __restrict__ X, const float* __restrict__ freqs,
                            int N, float scale_base, float sign) {
    int idx = blockIdx.x * blockDim.x + threadIdx.x;
    int total = BB * N * HH * (HDIM / 2);
    if (idx >= total) return;
    int p = idx & 31;             // pair index (HD/2 = 32)
    int h = (idx >> 5) & 15;      // head
    int row = idx >> 9;           // b*N + n
    int n = row % N;

    float t = (float)n;
    float fr = t * freqs[p];
    float c = cosf(fr), s = sinf(fr);
    float power = (t - (float)(N / 2)) / scale_base;
    float sv = (2.0f * (float)p + 0.4f * (float)HDIM) / (1.4f * (float)HDIM);
    float scale = powf(sv, power * sign);

    float* xp = X + (size_t)row * DD + h * HDIM + 2 * p;
    float x0 = xp[0], x1 = xp[1];
    xp[0] = (x0 * c - x1 * s) * scale;
    xp[1] = (x1 * c + x0 * s) * scale;
}

// ---------------------------------------------------------------------------
// Scores: S[b,h,q,k] = 0.125 * dot(Q[b,q,h,:], K[b,k,h,:])
// 64x64 output tile per block, k-dim = HD = 64 in 4 chunks of 16.
// ---------------------------------------------------------------------------
__global__ void scores_kernel(const float* __restrict__ Q, const float* __restrict__ Km,
                              float* __restrict__ attn) {
    int bh = blockIdx.z;
    int b = bh / HH, h = bh % HH;
    int q0 = blockIdx.y * 64, k0 = blockIdx.x * 64;
    const float* Qb = Q + (size_t)b * NQ * DD + h * HDIM;
    const float* Kb = Km + (size_t)b * NK * DD + h * HDIM;

    __shared__ float Qs[64][17];
    __shared__ float Ks[64][17];
    int tid = threadIdx.x;
    int tx = tid % 16, ty = tid / 16;
    float acc[4][4] = {};

    for (int kt = 0; kt < HDIM; kt += 16) {
#pragma unroll
        for (int i = 0; i < 4; i++) {
            int idx = tid + i * 256;
            int r = idx >> 4, c = idx & 15;
            Qs[r][c] = Qb[(size_t)(q0 + r) * DD + kt + c];
            Ks[r][c] = Kb[(size_t)(k0 + r) * DD + kt + c];
        }
        __syncthreads();
#pragma unroll
        for (int kk = 0; kk < 16; kk++) {
            float qr[4], kr[4];
#pragma unroll
            for (int i = 0; i < 4; i++) qr[i] = Qs[ty * 4 + i][kk];
#pragma unroll
            for (int j = 0; j < 4; j++) kr[j] = Ks[tx * 4 + j][kk];
#pragma unroll
            for (int i = 0; i < 4; i++)
#pragma unroll
                for (int j = 0; j < 4; j++) acc[i][j] += qr[i] * kr[j];
        }
        __syncthreads();
    }
    float* out = attn + (size_t)bh * NQ * NK;
    const float sc = 0.125f;  // HD^-0.5
#pragma unroll
    for (int i = 0; i < 4; i++)
#pragma unroll
        for (int j = 0; j < 4; j++)
            out[(size_t)(q0 + ty * 4 + i) * NK + (k0 + tx * 4 + j)] = acc[i][j] * sc;
}

// ---------------------------------------------------------------------------
// Row softmax in place. One block of 256 threads per row of length NK=2048.
// ---------------------------------------------------------------------------
__global__ void softmax_kernel(float* __restrict__ attn) {
    size_t row = blockIdx.x;
    float* p = attn + row * (size_t)NK;
    __shared__ float sm[NK];
    __shared__ float red[256];
    int t = threadIdx.x;

    float m = -1e30f;
    for (int i = t; i < NK; i += 256) {
        float v = p[i];
        sm[i] = v;
        m = fmaxf(m, v);
    }
    red[t] = m;
    __syncthreads();
    for (int s = 128; s > 0; s >>= 1) {
        if (t < s) red[t] = fmaxf(red[t], red[t + s]);
        __syncthreads();
    }
    m = red[0];
    __syncthreads();

    float sum = 0.0f;
    for (int i = t; i < NK; i += 256) {
        float e = expf(sm[i] - m);
        sm[i] = e;
        sum += e;
    }
    red[t] = sum;
    __syncthreads();
    for (int s = 128; s > 0; s >>= 1) {
        if (t < s) red[t] += red[t + s];
        __syncthreads();
    }
    float inv = 1.0f / red[0];
    for (int i = t; i < NK; i += 256) p[i] = sm[i] * inv;
}

// ---------------------------------------------------------------------------
// PV: O[b,q,h,:] = sum_k P[b,h,q,k] * V[b,k,h,:]
// Per (qtile, bh) block. M=2048, N=64 (one tile), K=2048 in chunks of 16.
// ---------------------------------------------------------------------------
__global__ void pv_kernel(const float* __restrict__ attn, const float* __restrict__ V,
                          float* __restrict__ O) {
    int bh = blockIdx.y;
    int b = bh / HH, h = bh % HH;
    int q0 = blockIdx.x * 64;
    const float* Pb = attn + (size_t)bh * NQ * NK;
    const float* Vb = V + (size_t)b * NK * DD + h * HDIM;

    __shared__ float Ps[64][17];
    __shared__ float Vs[16][65];
    int tid = threadIdx.x;
    int tx = tid % 16, ty = tid / 16;
    float acc[4][4] = {};

    for (int kt = 0; kt < NK; kt += 16) {
#pragma unroll
        for (int i = 0; i < 4; i++) {
            int idx = tid + i * 256;
            int r = idx >> 4, c = idx & 15;
            Ps[r][c] = Pb[(size_t)(q0 + r) * NK + kt + c];
            int vr = idx >> 6, vc = idx & 63;  // 16 rows x 64 cols
            Vs[vr][vc] = Vb[(size_t)(kt + vr) * DD + vc];
        }
        __syncthreads();
#pragma unroll
        for (int kk = 0; kk < 16; kk++) {
            float pr[4], vr[4];
#pragma unroll
            for (int i = 0; i < 4; i++) pr[i] = Ps[ty * 4 + i][kk];
#pragma unroll
            for (int j = 0; j < 4; j++) vr[j] = Vs[kk][tx * 4 + j];
#pragma unroll
            for (int i = 0; i < 4; i++)
#pragma unroll
                for (int j = 0; j < 4; j++) acc[i][j] += pr[i] * vr[j];
        }
        __syncthreads();
    }
#pragma unroll
    for (int i = 0; i < 4; i++)
#pragma unroll
        for (int j = 0; j < 4; j++)
            O[((size_t)b * NQ + q0 + ty * 4 + i) * DD + h * HDIM + tx * 4 + j] = acc[i][j];
}

// ---------------------------------------------------------------------------
extern "C" void kernel_launch(void* const* d_in, const int* in_sizes, int n_in,
                              void* d_out, int out_size) {
    const float* q_seq   = (const float*)d_in[0];
    const float* kv_seq  = (const float*)d_in[1];
    const float* Wq      = (const float*)d_in[2];
    const float* bq      = (const float*)d_in[3];
    const float* Wk      = (const float*)d_in[4];
    const float* bk      = (const float*)d_in[5];
    const float* Wv      = (const float*)d_in[6];
    const float* bv      = (const float*)d_in[7];
    const float* Wo      = (const float*)d_in[8];
    const float* bo      = (const float*)d_in[9];
    const float* freqs_q = (const float*)d_in[10];
    const float* freqs_kv= (const float*)d_in[11];

    float* out  = (float*)d_out;
    float* attn = out + (size_t)BB * NQ * DD;

    float *gQ, *gK, *gV, *gO;
    cudaGetSymbolAddress((void**)&gQ, g_Q);
    cudaGetSymbolAddress((void**)&gK, g_K);
    cudaGetSymbolAddress((void**)&gV, g_V);
    cudaGetSymbolAddress((void**)&gO, g_O);

    dim3 blk(256);
    dim3 gproj(DD / 64, (BB * NQ) / 64);

    gemm_bias<<<gproj, blk>>>(q_seq,  Wq, bq, gQ, BB * NQ, DD, DD);
    gemm_bias<<<gproj, blk>>>(kv_seq, Wk, bk, gK, BB * NK, DD, DD);
    gemm_bias<<<gproj, blk>>>(kv_seq, Wv, bv, gV, BB * NK, DD, DD);

    int nrope = BB * NQ * HH * (HDIM / 2);
    rope_kernel<<<nrope / 256, 256>>>(gQ, freqs_q,  NQ, (float)(2 * NQ),  1.0f);
    rope_kernel<<<nrope / 256, 256>>>(gK, freqs_kv, NK, (float)(2 * NK), -1.0f);

    scores_kernel<<<dim3(NK / 64, NQ / 64, BB * HH), blk>>>(gQ, gK, attn);
    softmax_kernel<<<BB * HH * NQ, 256>>>(attn);
    pv_kernel<<<dim3(NQ / 64, BB * HH), blk>>>(attn, gV, gO);

    gemm_bias<<<gproj, blk>>>(gO, Wo, bo, out, BB * NQ, DD, DD);
}

// round 2
// speedup vs baseline: 1.0013x; 1.0013x over previous
#include <cuda_runtime.h>
#include <cuda_bf16.h>
#include <math.h>

#define BB 2
#define NQ 2048
#define NK 2048
#define DD 1024
#define HH 16
#define HDIM 64

// Scratch (allocation-free: __device__ globals)
__device__ float g_Q[(size_t)BB * NQ * DD];
__device__ float g_K[(size_t)BB * NK * DD];
__device__ float g_V[(size_t)BB * NK * DD];
__device__ float g_O[(size_t)BB * NQ * DD];

// ---------------------------------------------------------------------------
// Generic tiled GEMM: Y[m][n] = sum_k X[m][k] * W[n][k] + b[n]
// X: (M,K) row-major, W: (N,K) row-major. 64x64 block tile, 16 k-tile,
// 256 threads, 4x4 per-thread micro-tile.
// ---------------------------------------------------------------------------
__global__ void gemm_bias(const float* __restrict__ X, const float* __restrict__ W,
                          const float* __restrict__ b, float* __restrict__ Y,
                          int M, int N, int K) {
    __shared__ float Xs[64][17];
    __shared__ float Ws[64][17];
    int tid = threadIdx.x;
    int tx = tid % 16, ty = tid / 16;
    int row0 = blockIdx.y * 64, col0 = blockIdx.x * 64;

    float acc[4][4] = {};
    for (int kt = 0; kt < K; kt += 16) {
#pragma unroll
        for (int i = 0; i < 4; i++) {
            int idx = tid + i * 256;
            int r = idx >> 4, c = idx & 15;
            Xs[r][c] = X[(size_t)(row0 + r) * K + kt + c];
            Ws[r][c] = W[(size_t)(col0 + r) * K + kt + c];
        }
        __syncthreads();
#pragma unroll
        for (int kk = 0; kk < 16; kk++) {
            float xr[4], wr[4];
#pragma unroll
            for (int i = 0; i < 4; i++) xr[i] = Xs[ty * 4 + i][kk];
#pragma unroll
            for (int j = 0; j < 4; j++) wr[j] = Ws[tx * 4 + j][kk];
#pragma unroll
            for (int i = 0; i < 4; i++)
#pragma unroll
                for (int j = 0; j < 4; j++) acc[i][j] += xr[i] * wr[j];
        }
        __syncthreads();
    }
#pragma unroll
    for (int i = 0; i < 4; i++)
#pragma unroll
        for (int j = 0; j < 4; j++) {
            int r = row0 + ty * 4 + i, c = col0 + tx * 4 + j;
            Y[(size_t)r * N + c] = acc[i][j] + b[c];
        }
}

// ---------------------------------------------------------------------------
// xpos RoPE, in place on (B, N, H*HD). One thread per (row, head, pair).
// ---------------------------------------------------------------------------
__global__ void rope_kernel(float* __restrict__ X, const float* __restrict__ freqs,
                            int N, float scale_base, float sign) {
    int idx = blockIdx.x * blockDim.x + threadIdx.x;
    int total = BB * N * HH * (HDIM / 2);
    if (idx >= total) return;
    int p = idx & 31;             // pair index (HD/2 = 32)
    int h = (idx >> 5) & 15;      // head
    int row = idx >> 9;           // b*N + n
    int n = row % N;

    float t = (float)n;
    float fr = t * freqs[p];
    float c = cosf(fr), s = sinf(fr);
    float power = (t - (float)(N / 2)) / scale_base;
    float sv = (2.0f * (float)p + 0.4f * (float)HDIM) / (1.4f * (float)HDIM);
    float scale = powf(sv, power * sign);

    float* xp = X + (size_t)row * DD + h * HDIM + 2 * p;
    float x0 = xp[0], x1 = xp[1];
    xp[0] = (x0 * c - x1 * s) * scale;
    xp[1] = (x1 * c + x0 * s) * scale;
}

// ---------------------------------------------------------------------------
// Scores: S[b,h,q,k] = 0.125 * dot(Q[b,q,h,:], K[b,k,h,:])
// 64x64 output tile per block, k-dim = HD = 64 in 4 chunks of 16.
// ---------------------------------------------------------------------------
__global__ void scores_kernel(const float* __restrict__ Q, const float* __restrict__ Km,
                              float* __restrict__ attn) {
    int bh = blockIdx.z;
    int b = bh / HH, h = bh % HH;
    int q0 = blockIdx.y * 64, k0 = blockIdx.x * 64;
    const float* Qb = Q + (size_t)b * NQ * DD + h * HDIM;
    const float* Kb = Km + (size_t)b * NK * DD + h * HDIM;

    __shared__ float Qs[64][17];
    __shared__ float Ks[64][17];
    int tid = threadIdx.x;
    int tx = tid % 16, ty = tid / 16;
    float acc[4][4] = {};

    for (int kt = 0; kt < HDIM; kt += 16) {
#pragma unroll
        for (int i = 0; i < 4; i++) {
            int idx = tid + i * 256;
            int r = idx >> 4, c = idx & 15;
            Qs[r][c] = Qb[(size_t)(q0 + r) * DD + kt + c];
            Ks[r][c] = Kb[(size_t)(k0 + r) * DD + kt + c];
        }
        __syncthreads();
#pragma unroll
        for (int kk = 0; kk < 16; kk++) {
            float qr[4], kr[4];
#pragma unroll
            for (int i = 0; i < 4; i++) qr[i] = Qs[ty * 4 + i][kk];
#pragma unroll
            for (int j = 0; j < 4; j++) kr[j] = Ks[tx * 4 + j][kk];
#pragma unroll
            for (int i = 0; i < 4; i++)
#pragma unroll
                for (int j = 0; j < 4; j++) acc[i][j] += qr[i] * kr[j];
        }
        __syncthreads();
    }
    float* out = attn + (size_t)bh * NQ * NK;
    const float sc = 0.125f;  // HD^-0.5
#pragma unroll
    for (int i = 0; i < 4; i++)
#pragma unroll
        for (int j = 0; j < 4; j++)
            out[(size_t)(q0 + ty * 4 + i) * NK + (k0 + tx * 4 + j)] = acc[i][j] * sc;
}

// ---------------------------------------------------------------------------
// Row softmax in place. One block of 256 threads per row of length NK=2048.
// ---------------------------------------------------------------------------
__global__ void softmax_kernel(float* __restrict__ attn) {
    size_t row = blockIdx.x;
    float* p = attn + row * (size_t)NK;
    __shared__ float sm[NK];
    __shared__ float red[256];
    int t = threadIdx.x;

    float m = -1e30f;
    for (int i = t; i < NK; i += 256) {
        float v = p[i];
        sm[i] = v;
        m = fmaxf(m, v);
    }
    red[t] = m;
    __syncthreads();
    for (int s = 128; s > 0; s >>= 1) {
        if (t < s) red[t] = fmaxf(red[t], red[t + s]);
        __syncthreads();
    }
    m = red[0];
    __syncthreads();

    float sum = 0.0f;
    for (int i = t; i < NK; i += 256) {
        float e = expf(sm[i] - m);
        sm[i] = e;
        sum += e;
    }
    red[t] = sum;
    __syncthreads();
    for (int s = 128; s > 0; s >>= 1) {
        if (t < s) red[t] += red[t + s];
        __syncthreads();
    }
    float inv = 1.0f / red[0];
    for (int i = t; i < NK; i += 256) p[i] = sm[i] * inv;
}

// ---------------------------------------------------------------------------
// PV: O[b,q,h,:] = sum_k P[b,h,q,k] * V[b,k,h,:]
// Per (qtile, bh) block. M=2048, N=64 (one tile), K=2048 in chunks of 16.
// ---------------------------------------------------------------------------
__global__ void pv_kernel(const float* __restrict__ attn, const float* __restrict__ V,
                          float* __restrict__ O) {
    int bh = blockIdx.y;
    int b = bh / HH, h = bh % HH;
    int q0 = blockIdx.x * 64;
    const float* Pb = attn + (size_t)bh * NQ * NK;
    const float* Vb = V + (size_t)b * NK * DD + h * HDIM;

    __shared__ float Ps[64][17];
    __shared__ float Vs[16][65];
    int tid = threadIdx.x;
    int tx = tid % 16, ty = tid / 16;
    float acc[4][4] = {};

    for (int kt = 0; kt < NK; kt += 16) {
#pragma unroll
        for (int i = 0; i < 4; i++) {
            int idx = tid + i * 256;
            int r = idx >> 4, c = idx & 15;
            Ps[r][c] = Pb[(size_t)(q0 + r) * NK + kt + c];
            int vr = idx >> 6, vc = idx & 63;  // 16 rows x 64 cols
            Vs[vr][vc] = Vb[(size_t)(kt + vr) * DD + vc];
        }
        __syncthreads();
#pragma unroll
        for (int kk = 0; kk < 16; kk++) {
            float pr[4], vr[4];
#pragma unroll
            for (int i = 0; i < 4; i++) pr[i] = Ps[ty * 4 + i][kk];
#pragma unroll
            for (int j = 0; j < 4; j++) vr[j] = Vs[kk][tx * 4 + j];
#pragma unroll
            for (int i = 0; i < 4; i++)
#pragma unroll
                for (int j = 0; j < 4; j++) acc[i][j] += pr[i] * vr[j];
        }
        __syncthreads();
    }
#pragma unroll
    for (int i = 0; i < 4; i++)
#pragma unroll
        for (int j = 0; j < 4; j++)
            O[((size_t)b * NQ + q0 + ty * 4 + i) * DD + h * HDIM + tx * 4 + j] = acc[i][j];
}

// ---------------------------------------------------------------------------
extern "C" void kernel_launch(void* const* d_in, const int* in_sizes, int n_in,
                              void* d_out, int out_size) {
    const float* q_seq   = (const float*)d_in[0];
    const float* kv_seq  = (const float*)d_in[1];
    const float* Wq      = (const float*)d_in[2];
    const float* bq      = (const float*)d_in[3];
    const float* Wk      = (const float*)d_in[4];
    const float* bk      = (const float*)d_in[5];
    const float* Wv      = (const float*)d_in[6];
    const float* bv      = (const float*)d_in[7];
    const float* Wo      = (const float*)d_in[8];
    const float* bo      = (const float*)d_in[9];
    const float* freqs_q = (const float*)d_in[10];
    const float* freqs_kv= (const float*)d_in[11];

    float* out  = (float*)d_out;
    float* attn = out + (size_t)BB * NQ * DD;

    float *gQ, *gK, *gV, *gO;
    cudaGetSymbolAddress((void**)&gQ, g_Q);
    cudaGetSymbolAddress((void**)&gK, g_K);
    cudaGetSymbolAddress((void**)&gV, g_V);
    cudaGetSymbolAddress((void**)&gO, g_O);

    dim3 blk(256);
    dim3 gproj(DD / 64, (BB * NQ) / 64);

    gemm_bias<<<gproj, blk>>>(q_seq,  Wq, bq, gQ, BB * NQ, DD, DD);
    gemm_bias<<<gproj, blk>>>(kv_seq, Wk, bk, gK, BB * NK, DD, DD);
    gemm_bias<<<gproj, blk>>>(kv_seq, Wv, bv, gV, BB * NK, DD, DD);

    int nrope = BB * NQ * HH * (HDIM / 2);
    rope_kernel<<<nrope / 256, 256>>>(gQ, freqs_q,  NQ, (float)(2 * NQ),  1.0f);
    rope_kernel<<<nrope / 256, 256>>>(gK, freqs_kv, NK, (float)(2 * NK), -1.0f);

    scores_kernel<<<dim3(NK / 64, NQ / 64, BB * HH), blk>>>(gQ, gK, attn);
    softmax_kernel<<<BB * HH * NQ, 256>>>(attn);
    pv_kernel<<<dim3(NQ / 64, BB * HH), blk>>>(attn, gV, gO);

    gemm_bias<<<gproj, blk>>>(gO, Wo, bo, out, BB * NQ, DD, DD);
}